// round 13
// baseline (speedup 1.0000x reference)
#include <cuda_runtime.h>
#include <cuda_bf16.h>
#include <cstdint>

typedef unsigned long long ull;
typedef unsigned int uint;

// ================= helpers =================
__device__ __forceinline__ void ffma2(ull& d, ull a, ull b) {
    asm("fma.rn.f32x2 %0, %1, %2, %0;" : "+l"(d) : "l"(a), "l"(b));
}
__device__ __forceinline__ ull pack2(float x, float y) {
    ull d; asm("mov.b64 %0, {%1, %2};" : "=l"(d) : "f"(x), "f"(y)); return d;
}
__device__ __forceinline__ float fast_sigmoid(float x) {
    float t;
    asm("tanh.approx.f32 %0, %1;" : "=f"(t) : "f"(x * 0.5f));
    return fmaf(t, 0.5f, 0.5f);
}
__device__ __forceinline__ uint bfpack(float x, float y) {
    __nv_bfloat16 bx = __float2bfloat16(x), by = __float2bfloat16(y);
    return (uint)__bfloat16_as_ushort(bx) | ((uint)__bfloat16_as_ushort(by) << 16);
}
__device__ __forceinline__ void split2(float x, float y, uint& hi, uint& lo) {
    __nv_bfloat16 hx = __float2bfloat16(x), hy = __float2bfloat16(y);
    hi = (uint)__bfloat16_as_ushort(hx) | ((uint)__bfloat16_as_ushort(hy) << 16);
    lo = bfpack(x - __bfloat162float(hx), y - __bfloat162float(hy));
}
__device__ __forceinline__ void mma_bf16(float* d, const uint* a, uint b0, uint b1) {
    asm volatile(
        "mma.sync.aligned.m16n8k16.row.col.f32.bf16.bf16.f32 "
        "{%0,%1,%2,%3}, {%4,%5,%6,%7}, {%8,%9}, {%0,%1,%2,%3};"
        : "+f"(d[0]), "+f"(d[1]), "+f"(d[2]), "+f"(d[3])
        : "r"(a[0]), "r"(a[1]), "r"(a[2]), "r"(a[3]), "r"(b0), "r"(b1));
}
__device__ __forceinline__ uint smem_u32(const void* p) {
    uint a;
    asm("{ .reg .u64 t; cvta.to.shared.u64 t, %1; cvt.u32.u64 %0, t; }" : "=r"(a) : "l"(p));
    return a;
}
__device__ __forceinline__ void cp_async16(uint saddr, const void* gptr) {
    asm volatile("cp.async.cg.shared.global [%0], [%1], 16;" :: "r"(saddr), "l"(gptr));
}
#define CP_COMMIT() asm volatile("cp.async.commit_group;" ::: "memory")
#define CP_WAIT0()  asm volatile("cp.async.wait_group 0;" ::: "memory")

// ================= constants =================
#define RDIM 384
#define SDIM 2048
#define CE   64
#define HC   64
#define QSCALE 0.35355339059327373f
#define BUFW  68
#define ASTW  36

// ================= scratch =================
__device__ float g_o[RDIM * HC];

// ============================================================================
// Fused attention kernel: one CTA per r, 256 threads (8 warps). (round-12,
// passing, f32/3-product precision path — untouched)
// ============================================================================
#define FA_KV    0
#define FA_MB    32768
#define FA_MASK  50176
#define FA_W     52224
#define FA_QRED  53376
#define FA_DRED  53888
#define FA_QPROJ 53896
#define FA_FLOATS 53968
#define FA_SMEM_BYTES (FA_FLOATS * 4)

__global__ void __launch_bounds__(256, 1)
fused_attn_kernel(const float* __restrict__ m, const float* __restrict__ mask,
                  const float* __restrict__ Wq, const float* __restrict__ Wk,
                  const float* __restrict__ Wv) {
    extern __shared__ __align__(16) float sfa[];
    float* kv_sh   = sfa + FA_KV;
    float* mbuf[2] = { sfa + FA_MB, sfa + FA_MB + 128 * BUFW };
    float* mask_sh = sfa + FA_MASK;
    uint*  wkv_hi  = (uint*)(sfa + FA_W);
    uint*  wkv_lo  = wkv_hi + 16 * ASTW;
    float* qred    = sfa + FA_QRED;
    float* dred    = sfa + FA_DRED;
    float* qproj   = sfa + FA_QPROJ;

    const int r    = blockIdx.x;
    const int tid  = threadIdx.x;
    const int lane = tid & 31;
    const int warp = tid >> 5;
    const int g    = lane >> 2;
    const int tg   = lane & 3;
    const int rowbase = warp * 16;

    const uint mbuf_u32[2] = { smem_u32(mbuf[0]), smem_u32(mbuf[1]) };

    for (int i = tid; i < 512; i += 256) {
        const int row = i >> 5, kp = i & 31;
        const float* W = (row < 8) ? (Wk + row * 64) : (Wv + (row - 8) * 64);
        float2 w = *(const float2*)(W + kp * 2);
        uint hi, lo; split2(w.x, w.y, hi, lo);
        wkv_hi[row * ASTW + kp] = hi;
        wkv_lo[row * ASTW + kp] = lo;
    }

    {
#pragma unroll
        for (int i = 0; i < 8; i++) {
            const int idx = tid + 256 * i;
            const int row = idx >> 4;
            const int c4  = (idx & 15) * 4;
            cp_async16(mbuf_u32[0] + (uint)(row * BUFW + c4) * 4,
                       m + ((size_t)r * SDIM + row) * CE + c4);
        }
        CP_COMMIT();
    }

    ull qn = 0ull;
    float qden = 0.0f;

    int cur = 0;
#pragma unroll 1
    for (int tile = 0; tile < 16; tile++, cur ^= 1) {
        const int sbase = tile * 128;

        CP_WAIT0();
        __syncthreads();

        if (tile + 1 < 16) {
            const int sbn = (tile + 1) * 128;
#pragma unroll
            for (int i = 0; i < 8; i++) {
                const int idx = tid + 256 * i;
                const int row = idx >> 4;
                const int c4  = (idx & 15) * 4;
                cp_async16(mbuf_u32[cur ^ 1] + (uint)(row * BUFW + c4) * 4,
                           m + ((size_t)r * SDIM + sbn + row) * CE + c4);
            }
            CP_COMMIT();
        }

        const float* buf = mbuf[cur];

        {
            const int sg = sbase + rowbase + (lane & 15);
            const float mskv = mask[(size_t)r * SDIM + sg];
            if (lane < 16) mask_sh[sg] = mskv;
#pragma unroll 8
            for (int i = 0; i < 16; i++) {
                const float msk = __shfl_sync(0xffffffffu, mskv, i);
                const ull mv = *(const ull*)&buf[(rowbase + i) * BUFW + 2 * lane];
                ffma2(qn, mv, pack2(msk, msk));
                qden += msk;
            }
        }

        float d[2][4];
#pragma unroll
        for (int nt = 0; nt < 2; nt++)
#pragma unroll
            for (int q = 0; q < 4; q++) d[nt][q] = 0.0f;

#pragma unroll
        for (int kt = 0; kt < 4; kt++) {
            uint ah[4], al[4];
            {
                const int r0 = rowbase + g;
                const float2 f0 = *(const float2*)&buf[r0 * BUFW + 16 * kt + 2 * tg];
                const float2 f1 = *(const float2*)&buf[(r0 + 8) * BUFW + 16 * kt + 2 * tg];
                const float2 f2 = *(const float2*)&buf[r0 * BUFW + 16 * kt + 2 * tg + 8];
                const float2 f3 = *(const float2*)&buf[(r0 + 8) * BUFW + 16 * kt + 2 * tg + 8];
                split2(f0.x, f0.y, ah[0], al[0]);
                split2(f1.x, f1.y, ah[1], al[1]);
                split2(f2.x, f2.y, ah[2], al[2]);
                split2(f3.x, f3.y, ah[3], al[3]);
            }
#pragma unroll
            for (int p = 0; p < 3; p++) {
                const uint* wb = (p == 1) ? wkv_lo : wkv_hi;
                const uint* af = (p == 2) ? al : ah;
#pragma unroll
                for (int nt = 0; nt < 2; nt++) {
                    const uint b0 = wb[(nt * 8 + g) * ASTW + kt * 8 + tg];
                    const uint b1 = wb[(nt * 8 + g) * ASTW + kt * 8 + tg + 4];
                    mma_bf16(d[nt], af, b0, b1);
                }
            }
        }

#pragma unroll
        for (int nt = 0; nt < 2; nt++) {
            const int c0 = nt * 8 + 2 * tg;
            const int s0 = sbase + rowbase + g;
            kv_sh[c0 * SDIM + s0]           = d[nt][0];
            kv_sh[(c0 + 1) * SDIM + s0]     = d[nt][1];
            kv_sh[c0 * SDIM + s0 + 8]       = d[nt][2];
            kv_sh[(c0 + 1) * SDIM + s0 + 8] = d[nt][3];
        }
    }

    ((ull*)qred)[warp * 32 + lane] = qn;
    if (lane == 0) dred[warp] = qden;
    __syncthreads();

    if (tid < 64) {
        float qs = 0.0f;
#pragma unroll
        for (int w = 0; w < 8; w++) qs += qred[w * 64 + tid];
        float dt = 0.0f;
#pragma unroll
        for (int w = 0; w < 8; w++) dt += dred[w];
        const float qp = qs / (dt + 1e-10f);
        qred[tid] = qp;
    }
    __syncthreads();
    if (tid < 64) {
        float acc = 0.0f;
        const float* wqr = Wq + tid * 64;
#pragma unroll
        for (int e = 0; e < 64; e++) acc = fmaf(qred[e], wqr[e], acc);
        qproj[tid] = acc * QSCALE;
    }
    __syncthreads();

    const int h = warp;
    float qh[8];
#pragma unroll
    for (int c = 0; c < 8; c++) qh[c] = qproj[h * 8 + c];

    float mx = -1e30f;
#pragma unroll 1
    for (int i = 0; i < 64; i++) {
        const int s = lane + 32 * i;
        float lg = (mask_sh[s] - 1.0f) * 1e9f;
#pragma unroll
        for (int c = 0; c < 8; c++) lg = fmaf(qh[c], kv_sh[c * SDIM + s], lg);
        mx = fmaxf(mx, lg);
    }
#pragma unroll
    for (int off = 16; off > 0; off >>= 1)
        mx = fmaxf(mx, __shfl_xor_sync(0xffffffffu, mx, off));

    float sum = 0.0f;
    float oacc[8];
#pragma unroll
    for (int c = 0; c < 8; c++) oacc[c] = 0.0f;
#pragma unroll 1
    for (int i = 0; i < 64; i++) {
        const int s = lane + 32 * i;
        float lg = (mask_sh[s] - 1.0f) * 1e9f;
#pragma unroll
        for (int c = 0; c < 8; c++) lg = fmaf(qh[c], kv_sh[c * SDIM + s], lg);
        const float e = __expf(lg - mx);
        sum += e;
#pragma unroll
        for (int c = 0; c < 8; c++)
            oacc[c] = fmaf(e, kv_sh[(8 + c) * SDIM + s], oacc[c]);
    }
#pragma unroll
    for (int off = 16; off > 0; off >>= 1) {
        sum += __shfl_xor_sync(0xffffffffu, sum, off);
#pragma unroll
        for (int c = 0; c < 8; c++)
            oacc[c] += __shfl_xor_sync(0xffffffffu, oacc[c], off);
    }
    if (lane == 0) {
        const float inv = 1.0f / sum;
#pragma unroll
        for (int c = 0; c < 8; c++)
            g_o[r * HC + h * 8 + c] = oacc[c] * inv;
    }
}

// ============================================================================
// Gate v5: round-8 loop structure, SINGLE bf16 product per GEMM.
// Error analysis: gate term is ~1.5% of |out|; single-bf16 adds ~5e-3 rel on
// that term -> ~1e-4 total rel err (threshold 1e-3). MMAs/tile 384 -> 128.
// ============================================================================
#define G_GRID 304
#define G_NT   (RDIM * (SDIM / 128))
#define G_BUF_FLOATS (128 * BUFW)
#define G_W_OFF  (2 * G_BUF_FLOATS)
#define G_SMEM_FLOATS (G_W_OFF + 2 * 64 * ASTW + 128)
#define G_SMEM_BYTES  (G_SMEM_FLOATS * 4)

__global__ void __launch_bounds__(128, 2)
gate_kernel(const float* __restrict__ m, const float* __restrict__ Wg,
            const float* __restrict__ bg, const float* __restrict__ Wo,
            const float* __restrict__ bo, const float* __restrict__ add_to,
            float* __restrict__ out) {
    extern __shared__ __align__(16) float sgf[];
    float* bufs[2] = { sgf, sgf + G_BUF_FLOATS };
    uint* wg_hi = (uint*)(sgf + G_W_OFF);
    uint* wo_hi = wg_hi + 64 * ASTW;
    float* bg_sh = (float*)(wo_hi + 64 * ASTW);
    float* bo_sh = bg_sh + 64;

    const int tid  = threadIdx.x;
    const int lane = tid & 31;
    const int warp = tid >> 5;
    const int g    = lane >> 2;
    const int tg   = lane & 3;
    const int rowbase = warp * 32;

    const uint buf_u32[2] = { smem_u32(bufs[0]), smem_u32(bufs[1]) };

    for (int i = tid; i < 2048; i += 128) {
        const int row = i >> 5, kp = i & 31;
        {
            float2 w = *(const float2*)(Wg + row * 64 + kp * 2);
            wg_hi[row * ASTW + kp] = bfpack(w.x, w.y);
        }
        {
            float2 w = *(const float2*)(Wo + row * 64 + kp * 2);
            wo_hi[row * ASTW + kp] = bfpack(w.x, w.y);
        }
    }
    if (tid < 64) {
        bg_sh[tid] = bg[tid];
        bo_sh[tid] = bo[tid];
    }

    int t0 = blockIdx.x;
    {
        const int r = t0 >> 4, sbase = (t0 & 15) * 128;
#pragma unroll
        for (int i = 0; i < 16; i++) {
            const int idx = tid + 128 * i;
            const int row = idx >> 4;
            const int c4  = (idx & 15) * 4;
            cp_async16(buf_u32[0] + (uint)(row * BUFW + c4) * 4,
                       m + ((size_t)r * SDIM + sbase + row) * CE + c4);
        }
        CP_COMMIT();
    }

    int cur = 0;
#pragma unroll 1
    for (int t = t0; t < G_NT; t += G_GRID, cur ^= 1) {
        const int r     = t >> 4;
        const int sbase = (t & 15) * 128;

        CP_WAIT0();
        __syncthreads();

        const int tn = t + G_GRID;
        if (tn < G_NT) {
            const int rn = tn >> 4, sbn = (tn & 15) * 128;
#pragma unroll
            for (int i = 0; i < 16; i++) {
                const int idx = tid + 128 * i;
                const int row = idx >> 4;
                const int c4  = (idx & 15) * 4;
                cp_async16(buf_u32[cur ^ 1] + (uint)(row * BUFW + c4) * 4,
                           m + ((size_t)rn * SDIM + sbn + row) * CE + c4);
            }
            CP_COMMIT();
        }

        const float* buf = bufs[cur];
        float d[2][8][4];

        // ===== GEMM1: gate logits = m @ Wg^T (single bf16 product) =====
#pragma unroll
        for (int mt = 0; mt < 2; mt++)
#pragma unroll
            for (int nt = 0; nt < 8; nt++)
#pragma unroll
                for (int q = 0; q < 4; q++) d[mt][nt][q] = 0.0f;

#pragma unroll
        for (int kt = 0; kt < 4; kt++) {
            uint ah[2][4];
#pragma unroll
            for (int mt = 0; mt < 2; mt++) {
                const int r0 = rowbase + mt * 16 + g;
                const float2 f0 = *(const float2*)&buf[r0 * BUFW + 16 * kt + 2 * tg];
                const float2 f1 = *(const float2*)&buf[(r0 + 8) * BUFW + 16 * kt + 2 * tg];
                const float2 f2 = *(const float2*)&buf[r0 * BUFW + 16 * kt + 2 * tg + 8];
                const float2 f3 = *(const float2*)&buf[(r0 + 8) * BUFW + 16 * kt + 2 * tg + 8];
                ah[mt][0] = bfpack(f0.x, f0.y);
                ah[mt][1] = bfpack(f1.x, f1.y);
                ah[mt][2] = bfpack(f2.x, f2.y);
                ah[mt][3] = bfpack(f3.x, f3.y);
            }
#pragma unroll
            for (int nt = 0; nt < 8; nt++) {
                const uint b0 = wg_hi[(nt * 8 + g) * ASTW + kt * 8 + tg];
                const uint b1 = wg_hi[(nt * 8 + g) * ASTW + kt * 8 + tg + 4];
                mma_bf16(d[0][nt], ah[0], b0, b1);
                mma_bf16(d[1][nt], ah[1], b0, b1);
            }
        }

        // ===== epilogue 1 (registers): t = sigmoid(d+bg)*o, bf16 =====
        uint th[2][8][2];
        {
            float ov0[8], ov1[8];
#pragma unroll
            for (int nt = 0; nt < 8; nt++) {
                const int c0 = nt * 8 + tg * 2;
                ov0[nt] = __ldg(&g_o[r * HC + c0]);
                ov1[nt] = __ldg(&g_o[r * HC + c0 + 1]);
            }
#pragma unroll
            for (int mt = 0; mt < 2; mt++) {
#pragma unroll
                for (int nt = 0; nt < 8; nt++) {
                    const int c0 = nt * 8 + tg * 2;
                    const float bg0 = bg_sh[c0], bg1 = bg_sh[c0 + 1];
                    const float t0 = fast_sigmoid(d[mt][nt][0] + bg0) * ov0[nt];
                    const float t1 = fast_sigmoid(d[mt][nt][1] + bg1) * ov1[nt];
                    const float t2 = fast_sigmoid(d[mt][nt][2] + bg0) * ov0[nt];
                    const float t3 = fast_sigmoid(d[mt][nt][3] + bg1) * ov1[nt];
                    th[mt][nt][0] = bfpack(t0, t1);
                    th[mt][nt][1] = bfpack(t2, t3);
                }
            }
        }

        // ===== GEMM2: out = t @ Wo^T (single bf16 product) =====
#pragma unroll
        for (int mt = 0; mt < 2; mt++)
#pragma unroll
            for (int nt = 0; nt < 8; nt++)
#pragma unroll
                for (int q = 0; q < 4; q++) d[mt][nt][q] = 0.0f;

#pragma unroll
        for (int kt = 0; kt < 4; kt++) {
            uint a[2][4];
#pragma unroll
            for (int mt = 0; mt < 2; mt++) {
                a[mt][0] = th[mt][2 * kt][0];
                a[mt][1] = th[mt][2 * kt][1];
                a[mt][2] = th[mt][2 * kt + 1][0];
                a[mt][3] = th[mt][2 * kt + 1][1];
            }
#pragma unroll
            for (int nt = 0; nt < 8; nt++) {
                const uint b0 = wo_hi[(nt * 8 + g) * ASTW + kt * 8 + tg];
                const uint b1 = wo_hi[(nt * 8 + g) * ASTW + kt * 8 + tg + 4];
                mma_bf16(d[0][nt], a[0], b0, b1);
                mma_bf16(d[1][nt], a[1], b0, b1);
            }
        }

        // ===== epilogue 2: out[s][r][:] = D + bo + add_to =====
#pragma unroll
        for (int mt = 0; mt < 2; mt++) {
#pragma unroll
            for (int nt = 0; nt < 8; nt++) {
                const int c0 = nt * 8 + tg * 2;
                const float bo0 = bo_sh[c0], bo1 = bo_sh[c0 + 1];
                const int r0 = rowbase + mt * 16 + g;
                {
                    const size_t base = ((size_t)(sbase + r0) * RDIM + r) * CE + c0;
                    const float2 av = *(const float2*)(add_to + base);
                    float2 ov;
                    ov.x = d[mt][nt][0] + bo0 + av.x;
                    ov.y = d[mt][nt][1] + bo1 + av.y;
                    *(float2*)(out + base) = ov;
                }
                {
                    const size_t base = ((size_t)(sbase + r0 + 8) * RDIM + r) * CE + c0;
                    const float2 av = *(const float2*)(add_to + base);
                    float2 ov;
                    ov.x = d[mt][nt][2] + bo0 + av.x;
                    ov.y = d[mt][nt][3] + bo1 + av.y;
                    *(float2*)(out + base) = ov;
                }
            }
        }
    }
}

// ============================================================================
extern "C" void kernel_launch(void* const* d_in, const int* in_sizes, int n_in,
                              void* d_out, int out_size) {
    const float* m      = (const float*)d_in[0];
    const float* mask   = (const float*)d_in[1];
    const float* Wq     = (const float*)d_in[2];
    const float* Wk     = (const float*)d_in[3];
    const float* Wv     = (const float*)d_in[4];
    const float* Wg     = (const float*)d_in[5];
    const float* bg     = (const float*)d_in[6];
    const float* Wo     = (const float*)d_in[7];
    const float* bo     = (const float*)d_in[8];
    const float* add_to = (const float*)d_in[9];
    float* out = (float*)d_out;

    cudaFuncSetAttribute(fused_attn_kernel, cudaFuncAttributeMaxDynamicSharedMemorySize,
                         FA_SMEM_BYTES);
    cudaFuncSetAttribute(gate_kernel, cudaFuncAttributeMaxDynamicSharedMemorySize,
                         G_SMEM_BYTES);

    fused_attn_kernel<<<RDIM, 256, FA_SMEM_BYTES>>>(m, mask, Wq, Wk, Wv);
    gate_kernel<<<G_GRID, 128, G_SMEM_BYTES>>>(m, Wg, bg, Wo, bo, add_to, out);
}

// round 14
// speedup vs baseline: 1.2729x; 1.2729x over previous
#include <cuda_runtime.h>
#include <cuda_bf16.h>
#include <cstdint>

typedef unsigned long long ull;
typedef unsigned int uint;

// ================= helpers =================
__device__ __forceinline__ void ffma2(ull& d, ull a, ull b) {
    asm("fma.rn.f32x2 %0, %1, %2, %0;" : "+l"(d) : "l"(a), "l"(b));
}
__device__ __forceinline__ ull pack2(float x, float y) {
    ull d; asm("mov.b64 %0, {%1, %2};" : "=l"(d) : "f"(x), "f"(y)); return d;
}
__device__ __forceinline__ float fast_sigmoid(float x) {
    float t;
    asm("tanh.approx.f32 %0, %1;" : "=f"(t) : "f"(x * 0.5f));
    return fmaf(t, 0.5f, 0.5f);
}
__device__ __forceinline__ uint bfpack(float x, float y) {
    __nv_bfloat16 bx = __float2bfloat16(x), by = __float2bfloat16(y);
    return (uint)__bfloat16_as_ushort(bx) | ((uint)__bfloat16_as_ushort(by) << 16);
}
__device__ __forceinline__ void split2(float x, float y, uint& hi, uint& lo) {
    __nv_bfloat16 hx = __float2bfloat16(x), hy = __float2bfloat16(y);
    hi = (uint)__bfloat16_as_ushort(hx) | ((uint)__bfloat16_as_ushort(hy) << 16);
    lo = bfpack(x - __bfloat162float(hx), y - __bfloat162float(hy));
}
__device__ __forceinline__ float2 bf2f(uint u) {
    float2 r;
    r.x = __bfloat162float(__ushort_as_bfloat16((unsigned short)(u & 0xffffu)));
    r.y = __bfloat162float(__ushort_as_bfloat16((unsigned short)(u >> 16)));
    return r;
}
__device__ __forceinline__ void mma_bf16(float* d, const uint* a, uint b0, uint b1) {
    asm volatile(
        "mma.sync.aligned.m16n8k16.row.col.f32.bf16.bf16.f32 "
        "{%0,%1,%2,%3}, {%4,%5,%6,%7}, {%8,%9}, {%0,%1,%2,%3};"
        : "+f"(d[0]), "+f"(d[1]), "+f"(d[2]), "+f"(d[3])
        : "r"(a[0]), "r"(a[1]), "r"(a[2]), "r"(a[3]), "r"(b0), "r"(b1));
}
__device__ __forceinline__ uint smem_u32(const void* p) {
    uint a;
    asm("{ .reg .u64 t; cvta.to.shared.u64 t, %1; cvt.u32.u64 %0, t; }" : "=r"(a) : "l"(p));
    return a;
}
__device__ __forceinline__ void cp_async16(uint saddr, const void* gptr) {
    asm volatile("cp.async.cg.shared.global [%0], [%1], 16;" :: "r"(saddr), "l"(gptr));
}
#define CP_COMMIT() asm volatile("cp.async.commit_group;" ::: "memory")
#define CP_WAIT0()  asm volatile("cp.async.wait_group 0;" ::: "memory")

// ================= constants =================
#define RDIM 384
#define SDIM 2048
#define CE   64
#define HC   64
#define QSCALE 0.35355339059327373f
#define BUFW  68
#define ASTW  36

// ================= scratch =================
__device__ float g_o[RDIM * HC];

// ============================================================================
// Fused attention v2: one CTA per r, 256 threads, 2 CTAs/SM.
// 64-row m tiles (32 tiles), warps 0-3 = kv HMMA (3-product), warps 4-7 =
// pooling+mask. kv stored in smem as packed bf16x2 pairs (64 KB).
// ============================================================================
// float offsets
#define FB_KVP   0                    // uint kvp[8][2048] = 16384 words
#define FB_MB    16384                // 2 x 64 x 68 = 8704
#define FB_MASK  25088                // 2048
#define FB_W     27136                // 1152 (wkv hi/lo)
#define FB_QRED  28288                // 4 x 64
#define FB_DRED  28544                // 16
#define FB_QPROJ 28560                // 64
#define FB_FLOATS 28624
#define FB_SMEM_BYTES (FB_FLOATS * 4)   // ~111.8 KB

__global__ void __launch_bounds__(256, 2)
fused_attn_kernel(const float* __restrict__ m, const float* __restrict__ mask,
                  const float* __restrict__ Wq, const float* __restrict__ Wk,
                  const float* __restrict__ Wv) {
    extern __shared__ __align__(16) float sfa[];
    uint*  kvp     = (uint*)(sfa + FB_KVP);     // pair cp: c=2cp,2cp+1 (cp<4 k, >=4 v)
    float* mbuf[2] = { sfa + FB_MB, sfa + FB_MB + 64 * BUFW };
    float* mask_sh = sfa + FB_MASK;
    uint*  wkv_hi  = (uint*)(sfa + FB_W);
    uint*  wkv_lo  = wkv_hi + 16 * ASTW;
    float* qred    = sfa + FB_QRED;
    float* dred    = sfa + FB_DRED;
    float* qproj   = sfa + FB_QPROJ;

    const int r    = blockIdx.x;
    const int tid  = threadIdx.x;
    const int lane = tid & 31;
    const int warp = tid >> 5;
    const int g    = lane >> 2;
    const int tg   = lane & 3;

    const uint mbuf_u32[2] = { smem_u32(mbuf[0]), smem_u32(mbuf[1]) };

    // stage Wkv hi/lo (rows 0..7 = Wk, 8..15 = Wv)
    for (int i = tid; i < 512; i += 256) {
        const int row = i >> 5, kp = i & 31;
        const float* W = (row < 8) ? (Wk + row * 64) : (Wv + (row - 8) * 64);
        float2 w = *(const float2*)(W + kp * 2);
        uint hi, lo; split2(w.x, w.y, hi, lo);
        wkv_hi[row * ASTW + kp] = hi;
        wkv_lo[row * ASTW + kp] = lo;
    }

    // prefetch tile 0 (64 rows x 64 f32 = 1024 x 16B chunks)
    {
#pragma unroll
        for (int i = 0; i < 4; i++) {
            const int idx = tid + 256 * i;
            const int row = idx >> 4;
            const int c4  = (idx & 15) * 4;
            cp_async16(mbuf_u32[0] + (uint)(row * BUFW + c4) * 4,
                       m + ((size_t)r * SDIM + row) * CE + c4);
        }
        CP_COMMIT();
    }

    ull qn = 0ull;          // pooling warps only
    float qden = 0.0f;

    int cur = 0;
#pragma unroll 1
    for (int tile = 0; tile < 32; tile++, cur ^= 1) {
        const int sbase = tile * 64;

        CP_WAIT0();
        __syncthreads();

        if (tile + 1 < 32) {
            const int sbn = (tile + 1) * 64;
#pragma unroll
            for (int i = 0; i < 4; i++) {
                const int idx = tid + 256 * i;
                const int row = idx >> 4;
                const int c4  = (idx & 15) * 4;
                cp_async16(mbuf_u32[cur ^ 1] + (uint)(row * BUFW + c4) * 4,
                           m + ((size_t)r * SDIM + sbn + row) * CE + c4);
            }
            CP_COMMIT();
        }

        const float* buf = mbuf[cur];

        if (warp >= 4) {
            // ---- pooling warps: 16 rows each ----
            const int prow = (warp - 4) * 16;
            const int sg = sbase + prow + (lane & 15);
            const float mskv = mask[(size_t)r * SDIM + sg];
            if (lane < 16) mask_sh[sg] = mskv;
#pragma unroll 8
            for (int i = 0; i < 16; i++) {
                const float msk = __shfl_sync(0xffffffffu, mskv, i);
                const ull mv = *(const ull*)&buf[(prow + i) * BUFW + 2 * lane];
                ffma2(qn, mv, pack2(msk, msk));
                qden += msk;
            }
        } else {
            // ---- GEMM warps: 16 rows each, 3-product bf16 HMMA ----
            const int rowbase = warp * 16;
            float d[2][4];
#pragma unroll
            for (int nt = 0; nt < 2; nt++)
#pragma unroll
                for (int q = 0; q < 4; q++) d[nt][q] = 0.0f;

#pragma unroll
            for (int kt = 0; kt < 4; kt++) {
                uint ah[4], al[4];
                {
                    const int r0 = rowbase + g;
                    const float2 f0 = *(const float2*)&buf[r0 * BUFW + 16 * kt + 2 * tg];
                    const float2 f1 = *(const float2*)&buf[(r0 + 8) * BUFW + 16 * kt + 2 * tg];
                    const float2 f2 = *(const float2*)&buf[r0 * BUFW + 16 * kt + 2 * tg + 8];
                    const float2 f3 = *(const float2*)&buf[(r0 + 8) * BUFW + 16 * kt + 2 * tg + 8];
                    split2(f0.x, f0.y, ah[0], al[0]);
                    split2(f1.x, f1.y, ah[1], al[1]);
                    split2(f2.x, f2.y, ah[2], al[2]);
                    split2(f3.x, f3.y, ah[3], al[3]);
                }
#pragma unroll
                for (int p = 0; p < 3; p++) {
                    const uint* wb = (p == 1) ? wkv_lo : wkv_hi;
                    const uint* af = (p == 2) ? al : ah;
#pragma unroll
                    for (int nt = 0; nt < 2; nt++) {
                        const uint b0 = wb[(nt * 8 + g) * ASTW + kt * 8 + tg];
                        const uint b1 = wb[(nt * 8 + g) * ASTW + kt * 8 + tg + 4];
                        mma_bf16(d[nt], af, b0, b1);
                    }
                }
            }

            // store as packed bf16 pairs: cp = nt*4+tg, rows s0 and s0+8
            const int s0 = sbase + rowbase + g;
#pragma unroll
            for (int nt = 0; nt < 2; nt++) {
                const int cp = nt * 4 + tg;
                kvp[cp * SDIM + s0]     = bfpack(d[nt][0], d[nt][1]);
                kvp[cp * SDIM + s0 + 8] = bfpack(d[nt][2], d[nt][3]);
            }
        }
    }

    // ---- phase B: pooling reduce -> q -> qproj ----
    if (warp >= 4) {
        ((ull*)qred)[(warp - 4) * 32 + lane] = qn;
        if (lane == 0) dred[warp - 4] = qden;
    }
    __syncthreads();

    if (tid < 64) {
        float qs = 0.0f;
#pragma unroll
        for (int w = 0; w < 4; w++) qs += qred[w * 64 + tid];
        float dt = 0.0f;
#pragma unroll
        for (int w = 0; w < 4; w++) dt += dred[w];
        const float qp = qs / (dt + 1e-10f);
        qred[tid] = qp;                 // reuse as qpool
    }
    __syncthreads();
    if (tid < 64) {
        float acc = 0.0f;
        const float* wqr = Wq + tid * 64;
#pragma unroll
        for (int e = 0; e < 64; e++) acc = fmaf(qred[e], wqr[e], acc);
        qproj[tid] = acc * QSCALE;
    }
    __syncthreads();

    // ---- phase C: warp = head, two-pass softmax over s (bf16 kv) ----
    const int h = warp;
    float qh[8];
#pragma unroll
    for (int c = 0; c < 8; c++) qh[c] = qproj[h * 8 + c];

    float mx = -1e30f;
#pragma unroll 1
    for (int i = 0; i < 64; i++) {
        const int s = lane + 32 * i;
        float lg = (mask_sh[s] - 1.0f) * 1e9f;
#pragma unroll
        for (int j = 0; j < 4; j++) {
            const float2 kv2 = bf2f(kvp[j * SDIM + s]);
            lg = fmaf(qh[2 * j], kv2.x, lg);
            lg = fmaf(qh[2 * j + 1], kv2.y, lg);
        }
        mx = fmaxf(mx, lg);
    }
#pragma unroll
    for (int off = 16; off > 0; off >>= 1)
        mx = fmaxf(mx, __shfl_xor_sync(0xffffffffu, mx, off));

    float sum = 0.0f;
    float oacc[8];
#pragma unroll
    for (int c = 0; c < 8; c++) oacc[c] = 0.0f;
#pragma unroll 1
    for (int i = 0; i < 64; i++) {
        const int s = lane + 32 * i;
        float lg = (mask_sh[s] - 1.0f) * 1e9f;
#pragma unroll
        for (int j = 0; j < 4; j++) {
            const float2 kv2 = bf2f(kvp[j * SDIM + s]);
            lg = fmaf(qh[2 * j], kv2.x, lg);
            lg = fmaf(qh[2 * j + 1], kv2.y, lg);
        }
        const float e = __expf(lg - mx);
        sum += e;
#pragma unroll
        for (int j = 0; j < 4; j++) {
            const float2 vv = bf2f(kvp[(4 + j) * SDIM + s]);
            oacc[2 * j]     = fmaf(e, vv.x, oacc[2 * j]);
            oacc[2 * j + 1] = fmaf(e, vv.y, oacc[2 * j + 1]);
        }
    }
#pragma unroll
    for (int off = 16; off > 0; off >>= 1) {
        sum += __shfl_xor_sync(0xffffffffu, sum, off);
#pragma unroll
        for (int c = 0; c < 8; c++)
            oacc[c] += __shfl_xor_sync(0xffffffffu, oacc[c], off);
    }
    if (lane == 0) {
        const float inv = 1.0f / sum;
#pragma unroll
        for (int c = 0; c < 8; c++)
            g_o[r * HC + h * 8 + c] = oacc[c] * inv;
    }
}

// ============================================================================
// Gate (round-12 proven config: 128 thr, 2 CTA/SM, 128-row tiles, 3-product
// bf16 hi/lo, m-only cp.async double buffer). Measured 179.8 us.
// ============================================================================
#define G_GRID 304
#define G_NT   (RDIM * (SDIM / 128))
#define G_BUF_FLOATS (128 * BUFW)
#define G_W_OFF  (2 * G_BUF_FLOATS)
#define G_SMEM_FLOATS (G_W_OFF + 4 * 64 * ASTW + 128)
#define G_SMEM_BYTES  (G_SMEM_FLOATS * 4)

__global__ void __launch_bounds__(128, 2)
gate_kernel(const float* __restrict__ m, const float* __restrict__ Wg,
            const float* __restrict__ bg, const float* __restrict__ Wo,
            const float* __restrict__ bo, const float* __restrict__ add_to,
            float* __restrict__ out) {
    extern __shared__ __align__(16) float sgf[];
    float* bufs[2] = { sgf, sgf + G_BUF_FLOATS };
    uint* wg_hi = (uint*)(sgf + G_W_OFF);
    uint* wg_lo = wg_hi + 64 * ASTW;
    uint* wo_hi = wg_lo + 64 * ASTW;
    uint* wo_lo = wo_hi + 64 * ASTW;
    float* bg_sh = (float*)(wo_lo + 64 * ASTW);
    float* bo_sh = bg_sh + 64;

    const int tid  = threadIdx.x;
    const int lane = tid & 31;
    const int warp = tid >> 5;
    const int g    = lane >> 2;
    const int tg   = lane & 3;
    const int rowbase = warp * 32;

    const uint buf_u32[2] = { smem_u32(bufs[0]), smem_u32(bufs[1]) };

    for (int i = tid; i < 2048; i += 128) {
        const int row = i >> 5, kp = i & 31;
        {
            float2 w = *(const float2*)(Wg + row * 64 + kp * 2);
            uint hi, lo; split2(w.x, w.y, hi, lo);
            wg_hi[row * ASTW + kp] = hi;
            wg_lo[row * ASTW + kp] = lo;
        }
        {
            float2 w = *(const float2*)(Wo + row * 64 + kp * 2);
            uint hi, lo; split2(w.x, w.y, hi, lo);
            wo_hi[row * ASTW + kp] = hi;
            wo_lo[row * ASTW + kp] = lo;
        }
    }
    if (tid < 64) {
        bg_sh[tid] = bg[tid];
        bo_sh[tid] = bo[tid];
    }

    int t0 = blockIdx.x;
    {
        const int r = t0 >> 4, sbase = (t0 & 15) * 128;
#pragma unroll
        for (int i = 0; i < 16; i++) {
            const int idx = tid + 128 * i;
            const int row = idx >> 4;
            const int c4  = (idx & 15) * 4;
            cp_async16(buf_u32[0] + (uint)(row * BUFW + c4) * 4,
                       m + ((size_t)r * SDIM + sbase + row) * CE + c4);
        }
        CP_COMMIT();
    }

    int cur = 0;
#pragma unroll 1
    for (int t = t0; t < G_NT; t += G_GRID, cur ^= 1) {
        const int r     = t >> 4;
        const int sbase = (t & 15) * 128;

        CP_WAIT0();
        __syncthreads();

        const int tn = t + G_GRID;
        if (tn < G_NT) {
            const int rn = tn >> 4, sbn = (tn & 15) * 128;
#pragma unroll
            for (int i = 0; i < 16; i++) {
                const int idx = tid + 128 * i;
                const int row = idx >> 4;
                const int c4  = (idx & 15) * 4;
                cp_async16(buf_u32[cur ^ 1] + (uint)(row * BUFW + c4) * 4,
                           m + ((size_t)rn * SDIM + sbn + row) * CE + c4);
            }
            CP_COMMIT();
        }

        const float* buf = bufs[cur];
        float d[2][8][4];

#pragma unroll
        for (int mt = 0; mt < 2; mt++)
#pragma unroll
            for (int nt = 0; nt < 8; nt++)
#pragma unroll
                for (int q = 0; q < 4; q++) d[mt][nt][q] = 0.0f;

#pragma unroll
        for (int kt = 0; kt < 4; kt++) {
            uint ah[2][4], al[2][4];
#pragma unroll
            for (int mt = 0; mt < 2; mt++) {
                const int r0 = rowbase + mt * 16 + g;
                const float2 f0 = *(const float2*)&buf[r0 * BUFW + 16 * kt + 2 * tg];
                const float2 f1 = *(const float2*)&buf[(r0 + 8) * BUFW + 16 * kt + 2 * tg];
                const float2 f2 = *(const float2*)&buf[r0 * BUFW + 16 * kt + 2 * tg + 8];
                const float2 f3 = *(const float2*)&buf[(r0 + 8) * BUFW + 16 * kt + 2 * tg + 8];
                split2(f0.x, f0.y, ah[mt][0], al[mt][0]);
                split2(f1.x, f1.y, ah[mt][1], al[mt][1]);
                split2(f2.x, f2.y, ah[mt][2], al[mt][2]);
                split2(f3.x, f3.y, ah[mt][3], al[mt][3]);
            }
#pragma unroll
            for (int p = 0; p < 3; p++) {
                const uint* wb = (p == 1) ? wg_lo : wg_hi;
                const uint (*af)[4] = (p == 2) ? al : ah;
#pragma unroll
                for (int nt = 0; nt < 8; nt++) {
                    const uint b0 = wb[(nt * 8 + g) * ASTW + kt * 8 + tg];
                    const uint b1 = wb[(nt * 8 + g) * ASTW + kt * 8 + tg + 4];
                    mma_bf16(d[0][nt], af[0], b0, b1);
                    mma_bf16(d[1][nt], af[1], b0, b1);
                }
            }
        }

        uint th[2][8][2], tl[2][8][2];
        {
            float ov0[8], ov1[8];
#pragma unroll
            for (int nt = 0; nt < 8; nt++) {
                const int c0 = nt * 8 + tg * 2;
                ov0[nt] = __ldg(&g_o[r * HC + c0]);
                ov1[nt] = __ldg(&g_o[r * HC + c0 + 1]);
            }
#pragma unroll
            for (int mt = 0; mt < 2; mt++) {
#pragma unroll
                for (int nt = 0; nt < 8; nt++) {
                    const int c0 = nt * 8 + tg * 2;
                    const float bg0 = bg_sh[c0], bg1 = bg_sh[c0 + 1];
                    const float t0 = fast_sigmoid(d[mt][nt][0] + bg0) * ov0[nt];
                    const float t1 = fast_sigmoid(d[mt][nt][1] + bg1) * ov1[nt];
                    const float t2 = fast_sigmoid(d[mt][nt][2] + bg0) * ov0[nt];
                    const float t3 = fast_sigmoid(d[mt][nt][3] + bg1) * ov1[nt];
                    split2(t0, t1, th[mt][nt][0], tl[mt][nt][0]);
                    split2(t2, t3, th[mt][nt][1], tl[mt][nt][1]);
                }
            }
        }

#pragma unroll
        for (int mt = 0; mt < 2; mt++)
#pragma unroll
            for (int nt = 0; nt < 8; nt++)
#pragma unroll
                for (int q = 0; q < 4; q++) d[mt][nt][q] = 0.0f;

#pragma unroll
        for (int p = 0; p < 3; p++) {
            const uint* wb = (p == 1) ? wo_lo : wo_hi;
#pragma unroll
            for (int kt = 0; kt < 4; kt++) {
                uint a[2][4];
#pragma unroll
                for (int mt = 0; mt < 2; mt++) {
                    if (p == 2) {
                        a[mt][0] = tl[mt][2 * kt][0];
                        a[mt][1] = tl[mt][2 * kt][1];
                        a[mt][2] = tl[mt][2 * kt + 1][0];
                        a[mt][3] = tl[mt][2 * kt + 1][1];
                    } else {
                        a[mt][0] = th[mt][2 * kt][0];
                        a[mt][1] = th[mt][2 * kt][1];
                        a[mt][2] = th[mt][2 * kt + 1][0];
                        a[mt][3] = th[mt][2 * kt + 1][1];
                    }
                }
#pragma unroll
                for (int nt = 0; nt < 8; nt++) {
                    const uint b0 = wb[(nt * 8 + g) * ASTW + kt * 8 + tg];
                    const uint b1 = wb[(nt * 8 + g) * ASTW + kt * 8 + tg + 4];
                    mma_bf16(d[0][nt], a[0], b0, b1);
                    mma_bf16(d[1][nt], a[1], b0, b1);
                }
            }
        }

#pragma unroll
        for (int mt = 0; mt < 2; mt++) {
#pragma unroll
            for (int nt = 0; nt < 8; nt++) {
                const int c0 = nt * 8 + tg * 2;
                const float bo0 = bo_sh[c0], bo1 = bo_sh[c0 + 1];
                const int r0 = rowbase + mt * 16 + g;
                {
                    const size_t base = ((size_t)(sbase + r0) * RDIM + r) * CE + c0;
                    const float2 av = *(const float2*)(add_to + base);
                    float2 ov;
                    ov.x = d[mt][nt][0] + bo0 + av.x;
                    ov.y = d[mt][nt][1] + bo1 + av.y;
                    *(float2*)(out + base) = ov;
                }
                {
                    const size_t base = ((size_t)(sbase + r0 + 8) * RDIM + r) * CE + c0;
                    const float2 av = *(const float2*)(add_to + base);
                    float2 ov;
                    ov.x = d[mt][nt][2] + bo0 + av.x;
                    ov.y = d[mt][nt][3] + bo1 + av.y;
                    *(float2*)(out + base) = ov;
                }
            }
        }
    }
}

// ============================================================================
extern "C" void kernel_launch(void* const* d_in, const int* in_sizes, int n_in,
                              void* d_out, int out_size) {
    const float* m      = (const float*)d_in[0];
    const float* mask   = (const float*)d_in[1];
    const float* Wq     = (const float*)d_in[2];
    const float* Wk     = (const float*)d_in[3];
    const float* Wv     = (const float*)d_in[4];
    const float* Wg     = (const float*)d_in[5];
    const float* bg     = (const float*)d_in[6];
    const float* Wo     = (const float*)d_in[7];
    const float* bo     = (const float*)d_in[8];
    const float* add_to = (const float*)d_in[9];
    float* out = (float*)d_out;

    cudaFuncSetAttribute(fused_attn_kernel, cudaFuncAttributeMaxDynamicSharedMemorySize,
                         FB_SMEM_BYTES);
    cudaFuncSetAttribute(gate_kernel, cudaFuncAttributeMaxDynamicSharedMemorySize,
                         G_SMEM_BYTES);

    fused_attn_kernel<<<RDIM, 256, FB_SMEM_BYTES>>>(m, mask, Wq, Wk, Wv);
    gate_kernel<<<G_GRID, 128, G_SMEM_BYTES>>>(m, Wg, bg, Wo, bo, add_to, out);
}

// round 15
// speedup vs baseline: 1.4148x; 1.1115x over previous
#include <cuda_runtime.h>
#include <cuda_bf16.h>
#include <cstdint>

typedef unsigned long long ull;
typedef unsigned int uint;

// ================= helpers =================
__device__ __forceinline__ void ffma2(ull& d, ull a, ull b) {
    asm("fma.rn.f32x2 %0, %1, %2, %0;" : "+l"(d) : "l"(a), "l"(b));
}
__device__ __forceinline__ ull pack2(float x, float y) {
    ull d; asm("mov.b64 %0, {%1, %2};" : "=l"(d) : "f"(x), "f"(y)); return d;
}
__device__ __forceinline__ float fast_sigmoid(float x) {
    float t;
    asm("tanh.approx.f32 %0, %1;" : "=f"(t) : "f"(x * 0.5f));
    return fmaf(t, 0.5f, 0.5f);
}
__device__ __forceinline__ uint bfpack(float x, float y) {
    __nv_bfloat16 bx = __float2bfloat16(x), by = __float2bfloat16(y);
    return (uint)__bfloat16_as_ushort(bx) | ((uint)__bfloat16_as_ushort(by) << 16);
}
__device__ __forceinline__ void split2(float x, float y, uint& hi, uint& lo) {
    __nv_bfloat16 hx = __float2bfloat16(x), hy = __float2bfloat16(y);
    hi = (uint)__bfloat16_as_ushort(hx) | ((uint)__bfloat16_as_ushort(hy) << 16);
    lo = bfpack(x - __bfloat162float(hx), y - __bfloat162float(hy));
}
__device__ __forceinline__ float2 bf2f(uint u) {
    float2 r;
    r.x = __bfloat162float(__ushort_as_bfloat16((unsigned short)(u & 0xffffu)));
    r.y = __bfloat162float(__ushort_as_bfloat16((unsigned short)(u >> 16)));
    return r;
}
__device__ __forceinline__ void mma_bf16(float* d, const uint* a, uint b0, uint b1) {
    asm volatile(
        "mma.sync.aligned.m16n8k16.row.col.f32.bf16.bf16.f32 "
        "{%0,%1,%2,%3}, {%4,%5,%6,%7}, {%8,%9}, {%0,%1,%2,%3};"
        : "+f"(d[0]), "+f"(d[1]), "+f"(d[2]), "+f"(d[3])
        : "r"(a[0]), "r"(a[1]), "r"(a[2]), "r"(a[3]), "r"(b0), "r"(b1));
}
__device__ __forceinline__ uint smem_u32(const void* p) {
    uint a;
    asm("{ .reg .u64 t; cvta.to.shared.u64 t, %1; cvt.u32.u64 %0, t; }" : "=r"(a) : "l"(p));
    return a;
}
__device__ __forceinline__ void cp_async16(uint saddr, const void* gptr) {
    asm volatile("cp.async.cg.shared.global [%0], [%1], 16;" :: "r"(saddr), "l"(gptr));
}
#define CP_COMMIT() asm volatile("cp.async.commit_group;" ::: "memory")
#define CP_WAIT0()  asm volatile("cp.async.wait_group 0;" ::: "memory")

// ================= constants =================
#define RDIM 384
#define SDIM 2048
#define CE   64
#define HC   64
#define QSCALE 0.35355339059327373f
#define BUFW  68
#define ASTW  36

// ================= scratch =================
__device__ float g_o[RDIM * HC];

// ============================================================================
// Fused attention v2 (round-14, passing): one CTA per r, 256 threads,
// 2 CTAs/SM, warp-specialized, bf16 kv in smem. UNCHANGED.
// ============================================================================
#define FB_KVP   0
#define FB_MB    16384
#define FB_MASK  25088
#define FB_W     27136
#define FB_QRED  28288
#define FB_DRED  28544
#define FB_QPROJ 28560
#define FB_FLOATS 28624
#define FB_SMEM_BYTES (FB_FLOATS * 4)

__global__ void __launch_bounds__(256, 2)
fused_attn_kernel(const float* __restrict__ m, const float* __restrict__ mask,
                  const float* __restrict__ Wq, const float* __restrict__ Wk,
                  const float* __restrict__ Wv) {
    extern __shared__ __align__(16) float sfa[];
    uint*  kvp     = (uint*)(sfa + FB_KVP);
    float* mbuf[2] = { sfa + FB_MB, sfa + FB_MB + 64 * BUFW };
    float* mask_sh = sfa + FB_MASK;
    uint*  wkv_hi  = (uint*)(sfa + FB_W);
    uint*  wkv_lo  = wkv_hi + 16 * ASTW;
    float* qred    = sfa + FB_QRED;
    float* dred    = sfa + FB_DRED;
    float* qproj   = sfa + FB_QPROJ;

    const int r    = blockIdx.x;
    const int tid  = threadIdx.x;
    const int lane = tid & 31;
    const int warp = tid >> 5;
    const int g    = lane >> 2;
    const int tg   = lane & 3;

    const uint mbuf_u32[2] = { smem_u32(mbuf[0]), smem_u32(mbuf[1]) };

    for (int i = tid; i < 512; i += 256) {
        const int row = i >> 5, kp = i & 31;
        const float* W = (row < 8) ? (Wk + row * 64) : (Wv + (row - 8) * 64);
        float2 w = *(const float2*)(W + kp * 2);
        uint hi, lo; split2(w.x, w.y, hi, lo);
        wkv_hi[row * ASTW + kp] = hi;
        wkv_lo[row * ASTW + kp] = lo;
    }

    {
#pragma unroll
        for (int i = 0; i < 4; i++) {
            const int idx = tid + 256 * i;
            const int row = idx >> 4;
            const int c4  = (idx & 15) * 4;
            cp_async16(mbuf_u32[0] + (uint)(row * BUFW + c4) * 4,
                       m + ((size_t)r * SDIM + row) * CE + c4);
        }
        CP_COMMIT();
    }

    ull qn = 0ull;
    float qden = 0.0f;

    int cur = 0;
#pragma unroll 1
    for (int tile = 0; tile < 32; tile++, cur ^= 1) {
        const int sbase = tile * 64;

        CP_WAIT0();
        __syncthreads();

        if (tile + 1 < 32) {
            const int sbn = (tile + 1) * 64;
#pragma unroll
            for (int i = 0; i < 4; i++) {
                const int idx = tid + 256 * i;
                const int row = idx >> 4;
                const int c4  = (idx & 15) * 4;
                cp_async16(mbuf_u32[cur ^ 1] + (uint)(row * BUFW + c4) * 4,
                           m + ((size_t)r * SDIM + sbn + row) * CE + c4);
            }
            CP_COMMIT();
        }

        const float* buf = mbuf[cur];

        if (warp >= 4) {
            const int prow = (warp - 4) * 16;
            const int sg = sbase + prow + (lane & 15);
            const float mskv = mask[(size_t)r * SDIM + sg];
            if (lane < 16) mask_sh[sg] = mskv;
#pragma unroll 8
            for (int i = 0; i < 16; i++) {
                const float msk = __shfl_sync(0xffffffffu, mskv, i);
                const ull mv = *(const ull*)&buf[(prow + i) * BUFW + 2 * lane];
                ffma2(qn, mv, pack2(msk, msk));
                qden += msk;
            }
        } else {
            const int rowbase = warp * 16;
            float d[2][4];
#pragma unroll
            for (int nt = 0; nt < 2; nt++)
#pragma unroll
                for (int q = 0; q < 4; q++) d[nt][q] = 0.0f;

#pragma unroll
            for (int kt = 0; kt < 4; kt++) {
                uint ah[4], al[4];
                {
                    const int r0 = rowbase + g;
                    const float2 f0 = *(const float2*)&buf[r0 * BUFW + 16 * kt + 2 * tg];
                    const float2 f1 = *(const float2*)&buf[(r0 + 8) * BUFW + 16 * kt + 2 * tg];
                    const float2 f2 = *(const float2*)&buf[r0 * BUFW + 16 * kt + 2 * tg + 8];
                    const float2 f3 = *(const float2*)&buf[(r0 + 8) * BUFW + 16 * kt + 2 * tg + 8];
                    split2(f0.x, f0.y, ah[0], al[0]);
                    split2(f1.x, f1.y, ah[1], al[1]);
                    split2(f2.x, f2.y, ah[2], al[2]);
                    split2(f3.x, f3.y, ah[3], al[3]);
                }
#pragma unroll
                for (int p = 0; p < 3; p++) {
                    const uint* wb = (p == 1) ? wkv_lo : wkv_hi;
                    const uint* af = (p == 2) ? al : ah;
#pragma unroll
                    for (int nt = 0; nt < 2; nt++) {
                        const uint b0 = wb[(nt * 8 + g) * ASTW + kt * 8 + tg];
                        const uint b1 = wb[(nt * 8 + g) * ASTW + kt * 8 + tg + 4];
                        mma_bf16(d[nt], af, b0, b1);
                    }
                }
            }

            const int s0 = sbase + rowbase + g;
#pragma unroll
            for (int nt = 0; nt < 2; nt++) {
                const int cp = nt * 4 + tg;
                kvp[cp * SDIM + s0]     = bfpack(d[nt][0], d[nt][1]);
                kvp[cp * SDIM + s0 + 8] = bfpack(d[nt][2], d[nt][3]);
            }
        }
    }

    if (warp >= 4) {
        ((ull*)qred)[(warp - 4) * 32 + lane] = qn;
        if (lane == 0) dred[warp - 4] = qden;
    }
    __syncthreads();

    if (tid < 64) {
        float qs = 0.0f;
#pragma unroll
        for (int w = 0; w < 4; w++) qs += qred[w * 64 + tid];
        float dt = 0.0f;
#pragma unroll
        for (int w = 0; w < 4; w++) dt += dred[w];
        const float qp = qs / (dt + 1e-10f);
        qred[tid] = qp;
    }
    __syncthreads();
    if (tid < 64) {
        float acc = 0.0f;
        const float* wqr = Wq + tid * 64;
#pragma unroll
        for (int e = 0; e < 64; e++) acc = fmaf(qred[e], wqr[e], acc);
        qproj[tid] = acc * QSCALE;
    }
    __syncthreads();

    const int h = warp;
    float qh[8];
#pragma unroll
    for (int c = 0; c < 8; c++) qh[c] = qproj[h * 8 + c];

    float mx = -1e30f;
#pragma unroll 1
    for (int i = 0; i < 64; i++) {
        const int s = lane + 32 * i;
        float lg = (mask_sh[s] - 1.0f) * 1e9f;
#pragma unroll
        for (int j = 0; j < 4; j++) {
            const float2 kv2 = bf2f(kvp[j * SDIM + s]);
            lg = fmaf(qh[2 * j], kv2.x, lg);
            lg = fmaf(qh[2 * j + 1], kv2.y, lg);
        }
        mx = fmaxf(mx, lg);
    }
#pragma unroll
    for (int off = 16; off > 0; off >>= 1)
        mx = fmaxf(mx, __shfl_xor_sync(0xffffffffu, mx, off));

    float sum = 0.0f;
    float oacc[8];
#pragma unroll
    for (int c = 0; c < 8; c++) oacc[c] = 0.0f;
#pragma unroll 1
    for (int i = 0; i < 64; i++) {
        const int s = lane + 32 * i;
        float lg = (mask_sh[s] - 1.0f) * 1e9f;
#pragma unroll
        for (int j = 0; j < 4; j++) {
            const float2 kv2 = bf2f(kvp[j * SDIM + s]);
            lg = fmaf(qh[2 * j], kv2.x, lg);
            lg = fmaf(qh[2 * j + 1], kv2.y, lg);
        }
        const float e = __expf(lg - mx);
        sum += e;
#pragma unroll
        for (int j = 0; j < 4; j++) {
            const float2 vv = bf2f(kvp[(4 + j) * SDIM + s]);
            oacc[2 * j]     = fmaf(e, vv.x, oacc[2 * j]);
            oacc[2 * j + 1] = fmaf(e, vv.y, oacc[2 * j + 1]);
        }
    }
#pragma unroll
    for (int off = 16; off > 0; off >>= 1) {
        sum += __shfl_xor_sync(0xffffffffu, sum, off);
#pragma unroll
        for (int c = 0; c < 8; c++)
            oacc[c] += __shfl_xor_sync(0xffffffffu, oacc[c], off);
    }
    if (lane == 0) {
        const float inv = 1.0f / sum;
#pragma unroll
        for (int c = 0; c < 8; c++)
            g_o[r * HC + h * 8 + c] = oacc[c] * inv;
    }
}

// ============================================================================
// Gate v6: 4 CTAs/SM. 128 threads, warp owns 16 rows of a 64-row tile.
// SINGLE bf16 product per GEMM (proven rel_err 4.3e-5, zero perf cost).
// smem ~54 KB -> 4 CTAs/SM = 16 warps for latency hiding.
// ============================================================================
#define G_GRID 608
#define G_ROWS 64
#define G_NT   (RDIM * (SDIM / G_ROWS))          // 12288
#define G_BUF_FLOATS (G_ROWS * BUFW)             // 4352
#define G_W_OFF  (2 * G_BUF_FLOATS)
#define G_SMEM_FLOATS (G_W_OFF + 2 * 64 * ASTW + 128)
#define G_SMEM_BYTES  (G_SMEM_FLOATS * 4)        // ~53.8 KB

__global__ void __launch_bounds__(128, 4)
gate_kernel(const float* __restrict__ m, const float* __restrict__ Wg,
            const float* __restrict__ bg, const float* __restrict__ Wo,
            const float* __restrict__ bo, const float* __restrict__ add_to,
            float* __restrict__ out) {
    extern __shared__ __align__(16) float sgf[];
    float* bufs[2] = { sgf, sgf + G_BUF_FLOATS };
    uint* wg_hi = (uint*)(sgf + G_W_OFF);
    uint* wo_hi = wg_hi + 64 * ASTW;
    float* bg_sh = (float*)(wo_hi + 64 * ASTW);
    float* bo_sh = bg_sh + 64;

    const int tid  = threadIdx.x;
    const int lane = tid & 31;
    const int warp = tid >> 5;
    const int g    = lane >> 2;
    const int tg   = lane & 3;
    const int rowbase = warp * 16;     // 4 warps x 16 rows = 64

    const uint buf_u32[2] = { smem_u32(bufs[0]), smem_u32(bufs[1]) };

    // stage weights (hi only) + biases once
    for (int i = tid; i < 2048; i += 128) {
        const int row = i >> 5, kp = i & 31;
        {
            float2 w = *(const float2*)(Wg + row * 64 + kp * 2);
            wg_hi[row * ASTW + kp] = bfpack(w.x, w.y);
        }
        {
            float2 w = *(const float2*)(Wo + row * 64 + kp * 2);
            wo_hi[row * ASTW + kp] = bfpack(w.x, w.y);
        }
    }
    if (tid < 64) {
        bg_sh[tid] = bg[tid];
        bo_sh[tid] = bo[tid];
    }

    const int t0 = blockIdx.x;
    if (t0 < G_NT) {
        const int r = t0 >> 5, sbase = (t0 & 31) * G_ROWS;
#pragma unroll
        for (int i = 0; i < 8; i++) {
            const int idx = tid + 128 * i;
            const int row = idx >> 4;
            const int c4  = (idx & 15) * 4;
            cp_async16(buf_u32[0] + (uint)(row * BUFW + c4) * 4,
                       m + ((size_t)r * SDIM + sbase + row) * CE + c4);
        }
        CP_COMMIT();
    }

    int cur = 0;
#pragma unroll 1
    for (int t = t0; t < G_NT; t += G_GRID, cur ^= 1) {
        const int r     = t >> 5;
        const int sbase = (t & 31) * G_ROWS;

        CP_WAIT0();
        __syncthreads();

        const int tn = t + G_GRID;
        if (tn < G_NT) {
            const int rn = tn >> 5, sbn = (tn & 31) * G_ROWS;
#pragma unroll
            for (int i = 0; i < 8; i++) {
                const int idx = tid + 128 * i;
                const int row = idx >> 4;
                const int c4  = (idx & 15) * 4;
                cp_async16(buf_u32[cur ^ 1] + (uint)(row * BUFW + c4) * 4,
                           m + ((size_t)rn * SDIM + sbn + row) * CE + c4);
            }
            CP_COMMIT();
        }

        const float* buf = bufs[cur];
        float d[8][4];

        // ===== GEMM1: gate logits = m @ Wg^T (single bf16 product) =====
#pragma unroll
        for (int nt = 0; nt < 8; nt++)
#pragma unroll
            for (int q = 0; q < 4; q++) d[nt][q] = 0.0f;

#pragma unroll
        for (int kt = 0; kt < 4; kt++) {
            uint ah[4];
            {
                const int r0 = rowbase + g;
                const float2 f0 = *(const float2*)&buf[r0 * BUFW + 16 * kt + 2 * tg];
                const float2 f1 = *(const float2*)&buf[(r0 + 8) * BUFW + 16 * kt + 2 * tg];
                const float2 f2 = *(const float2*)&buf[r0 * BUFW + 16 * kt + 2 * tg + 8];
                const float2 f3 = *(const float2*)&buf[(r0 + 8) * BUFW + 16 * kt + 2 * tg + 8];
                ah[0] = bfpack(f0.x, f0.y);
                ah[1] = bfpack(f1.x, f1.y);
                ah[2] = bfpack(f2.x, f2.y);
                ah[3] = bfpack(f3.x, f3.y);
            }
#pragma unroll
            for (int nt = 0; nt < 8; nt++) {
                const uint b0 = wg_hi[(nt * 8 + g) * ASTW + kt * 8 + tg];
                const uint b1 = wg_hi[(nt * 8 + g) * ASTW + kt * 8 + tg + 4];
                mma_bf16(d[nt], ah, b0, b1);
            }
        }

        // ===== epilogue 1 (registers): t = sigmoid(d+bg)*o, bf16 =====
        uint th[8][2];
#pragma unroll
        for (int nt = 0; nt < 8; nt++) {
            const int c0 = nt * 8 + tg * 2;
            const float ov0 = __ldg(&g_o[r * HC + c0]);
            const float ov1 = __ldg(&g_o[r * HC + c0 + 1]);
            const float bg0 = bg_sh[c0], bg1 = bg_sh[c0 + 1];
            const float t0v = fast_sigmoid(d[nt][0] + bg0) * ov0;
            const float t1v = fast_sigmoid(d[nt][1] + bg1) * ov1;
            const float t2v = fast_sigmoid(d[nt][2] + bg0) * ov0;
            const float t3v = fast_sigmoid(d[nt][3] + bg1) * ov1;
            th[nt][0] = bfpack(t0v, t1v);
            th[nt][1] = bfpack(t2v, t3v);
        }

        // ===== GEMM2: out = t @ Wo^T (single bf16 product) =====
#pragma unroll
        for (int nt = 0; nt < 8; nt++)
#pragma unroll
            for (int q = 0; q < 4; q++) d[nt][q] = 0.0f;

#pragma unroll
        for (int kt = 0; kt < 4; kt++) {
            uint a[4];
            a[0] = th[2 * kt][0];
            a[1] = th[2 * kt][1];
            a[2] = th[2 * kt + 1][0];
            a[3] = th[2 * kt + 1][1];
#pragma unroll
            for (int nt = 0; nt < 8; nt++) {
                const uint b0 = wo_hi[(nt * 8 + g) * ASTW + kt * 8 + tg];
                const uint b1 = wo_hi[(nt * 8 + g) * ASTW + kt * 8 + tg + 4];
                mma_bf16(d[nt], a, b0, b1);
            }
        }

        // ===== epilogue 2: out[s][r][:] = D + bo + add_to =====
#pragma unroll
        for (int nt = 0; nt < 8; nt++) {
            const int c0 = nt * 8 + tg * 2;
            const float bo0 = bo_sh[c0], bo1 = bo_sh[c0 + 1];
            const int r0 = rowbase + g;
            {
                const size_t base = ((size_t)(sbase + r0) * RDIM + r) * CE + c0;
                const float2 av = *(const float2*)(add_to + base);
                float2 ov;
                ov.x = d[nt][0] + bo0 + av.x;
                ov.y = d[nt][1] + bo1 + av.y;
                *(float2*)(out + base) = ov;
            }
            {
                const size_t base = ((size_t)(sbase + r0 + 8) * RDIM + r) * CE + c0;
                const float2 av = *(const float2*)(add_to + base);
                float2 ov;
                ov.x = d[nt][2] + bo0 + av.x;
                ov.y = d[nt][3] + bo1 + av.y;
                *(float2*)(out + base) = ov;
            }
        }
    }
}

// ============================================================================
extern "C" void kernel_launch(void* const* d_in, const int* in_sizes, int n_in,
                              void* d_out, int out_size) {
    const float* m      = (const float*)d_in[0];
    const float* mask   = (const float*)d_in[1];
    const float* Wq     = (const float*)d_in[2];
    const float* Wk     = (const float*)d_in[3];
    const float* Wv     = (const float*)d_in[4];
    const float* Wg     = (const float*)d_in[5];
    const float* bg     = (const float*)d_in[6];
    const float* Wo     = (const float*)d_in[7];
    const float* bo     = (const float*)d_in[8];
    const float* add_to = (const float*)d_in[9];
    float* out = (float*)d_out;

    cudaFuncSetAttribute(fused_attn_kernel, cudaFuncAttributeMaxDynamicSharedMemorySize,
                         FB_SMEM_BYTES);
    cudaFuncSetAttribute(gate_kernel, cudaFuncAttributeMaxDynamicSharedMemorySize,
                         G_SMEM_BYTES);

    fused_attn_kernel<<<RDIM, 256, FB_SMEM_BYTES>>>(m, mask, Wq, Wk, Wv);
    gate_kernel<<<G_GRID, 128, G_SMEM_BYTES>>>(m, Wg, bg, Wo, bo, add_to, out);
}

// round 17
// speedup vs baseline: 1.5677x; 1.1081x over previous
#include <cuda_runtime.h>
#include <cuda_bf16.h>
#include <cstdint>

typedef unsigned long long ull;
typedef unsigned int uint;

// ================= helpers =================
__device__ __forceinline__ void ffma2(ull& d, ull a, ull b) {
    asm("fma.rn.f32x2 %0, %1, %2, %0;" : "+l"(d) : "l"(a), "l"(b));
}
__device__ __forceinline__ ull pack2(float x, float y) {
    ull d; asm("mov.b64 %0, {%1, %2};" : "=l"(d) : "f"(x), "f"(y)); return d;
}
__device__ __forceinline__ float fast_sigmoid(float x) {
    float t;
    asm("tanh.approx.f32 %0, %1;" : "=f"(t) : "f"(x * 0.5f));
    return fmaf(t, 0.5f, 0.5f);
}
__device__ __forceinline__ uint bfpack(float x, float y) {
    __nv_bfloat16 bx = __float2bfloat16(x), by = __float2bfloat16(y);
    return (uint)__bfloat16_as_ushort(bx) | ((uint)__bfloat16_as_ushort(by) << 16);
}
__device__ __forceinline__ void split2(float x, float y, uint& hi, uint& lo) {
    __nv_bfloat16 hx = __float2bfloat16(x), hy = __float2bfloat16(y);
    hi = (uint)__bfloat16_as_ushort(hx) | ((uint)__bfloat16_as_ushort(hy) << 16);
    lo = bfpack(x - __bfloat162float(hx), y - __bfloat162float(hy));
}
__device__ __forceinline__ float2 bf2f(uint u) {
    float2 r;
    r.x = __bfloat162float(__ushort_as_bfloat16((unsigned short)(u & 0xffffu)));
    r.y = __bfloat162float(__ushort_as_bfloat16((unsigned short)(u >> 16)));
    return r;
}
__device__ __forceinline__ void mma_bf16(float* d, const uint* a, uint b0, uint b1) {
    asm volatile(
        "mma.sync.aligned.m16n8k16.row.col.f32.bf16.bf16.f32 "
        "{%0,%1,%2,%3}, {%4,%5,%6,%7}, {%8,%9}, {%0,%1,%2,%3};"
        : "+f"(d[0]), "+f"(d[1]), "+f"(d[2]), "+f"(d[3])
        : "r"(a[0]), "r"(a[1]), "r"(a[2]), "r"(a[3]), "r"(b0), "r"(b1));
}
__device__ __forceinline__ uint smem_u32(const void* p) {
    uint a;
    asm("{ .reg .u64 t; cvta.to.shared.u64 t, %1; cvt.u32.u64 %0, t; }" : "=r"(a) : "l"(p));
    return a;
}
__device__ __forceinline__ void cp_async16(uint saddr, const void* gptr) {
    asm volatile("cp.async.cg.shared.global [%0], [%1], 16;" :: "r"(saddr), "l"(gptr));
}
#define CP_COMMIT() asm volatile("cp.async.commit_group;" ::: "memory")
#define CP_WAIT0()  asm volatile("cp.async.wait_group 0;" ::: "memory")

// ================= constants =================
#define RDIM 384
#define SDIM 2048
#define CE   64
#define HC   64
#define QSCALE 0.35355339059327373f
#define BUFW  68
#define ASTW  36
#define MEGA_GRID 304

// ================= scratch =================
__device__ float g_o[RDIM * HC];
__device__ volatile int g_flag[RDIM];
__device__ int g_ctr;

// ============================================================================
// Reset: clear flags + gate work counter. Same stream, before mega kernel.
// ============================================================================
__global__ void reset_kernel() {
    if (threadIdx.x < RDIM) g_flag[threadIdx.x] = 0;
    if (threadIdx.x == 0) g_ctr = 0;
}

// ============================================================================
// Mega kernel: phase 1 = fused attention for this CTA's r's (round-14 body),
// phase 2 = gate tiles from an atomic counter with per-r flag spin.
// 304 CTAs x 256 threads, 2 CTAs/SM (single wave => deadlock-free).
// ============================================================================
// ---- attn-phase smem layout (floats) ----
#define FB_KVP   0
#define FB_MB    16384
#define FB_MASK  25088
#define FB_W     27136
#define FB_QRED  28288
#define FB_DRED  28544
#define FB_QPROJ 28560
#define FB_FLOATS 28624
#define MG_SMEM_BYTES (FB_FLOATS * 4)     // 114496 B

// ---- gate-phase smem layout (floats, reuses same buffer) ----
#define GB_MB   0                          // 2 x 128 x 68 = 17408
#define GB_W    17408                      // wg_hi 2304 + wo_hi 2304 words
#define GB_VEC  22016                      // bg 64, bo 64
#define GB_TS   22144                      // int tshare[2]
#define G_NT    (RDIM * (SDIM / 128))      // 6144 tiles

__global__ void __launch_bounds__(256, 2)
mega_kernel(const float* __restrict__ m, const float* __restrict__ mask,
            const float* __restrict__ Wq, const float* __restrict__ Wk,
            const float* __restrict__ Wv, const float* __restrict__ Wg,
            const float* __restrict__ bg, const float* __restrict__ Wo,
            const float* __restrict__ bo, const float* __restrict__ add_to,
            float* __restrict__ out) {
    extern __shared__ __align__(16) float sfa[];

    const int bid  = blockIdx.x;
    const int tid  = threadIdx.x;
    const int lane = tid & 31;
    const int warp = tid >> 5;
    const int g    = lane >> 2;
    const int tg   = lane & 3;

    // ======================= PHASE 1: attention =======================
    {
        uint*  kvp     = (uint*)(sfa + FB_KVP);
        float* mbuf[2] = { sfa + FB_MB, sfa + FB_MB + 64 * BUFW };
        float* mask_sh = sfa + FB_MASK;
        uint*  wkv_hi  = (uint*)(sfa + FB_W);
        uint*  wkv_lo  = wkv_hi + 16 * ASTW;
        float* qred    = sfa + FB_QRED;
        float* dred    = sfa + FB_DRED;
        float* qproj   = sfa + FB_QPROJ;
        const uint mbuf_u32[2] = { smem_u32(mbuf[0]), smem_u32(mbuf[1]) };

        for (int i = tid; i < 512; i += 256) {
            const int row = i >> 5, kp = i & 31;
            const float* W = (row < 8) ? (Wk + row * 64) : (Wv + (row - 8) * 64);
            float2 w = *(const float2*)(W + kp * 2);
            uint hi, lo; split2(w.x, w.y, hi, lo);
            wkv_hi[row * ASTW + kp] = hi;
            wkv_lo[row * ASTW + kp] = lo;
        }
        __syncthreads();

#pragma unroll 1
        for (int r = bid; r < RDIM; r += MEGA_GRID) {
            // prefetch tile 0
            {
#pragma unroll
                for (int i = 0; i < 4; i++) {
                    const int idx = tid + 256 * i;
                    const int row = idx >> 4;
                    const int c4  = (idx & 15) * 4;
                    cp_async16(mbuf_u32[0] + (uint)(row * BUFW + c4) * 4,
                               m + ((size_t)r * SDIM + row) * CE + c4);
                }
                CP_COMMIT();
            }

            ull qn = 0ull;
            float qden = 0.0f;

            int cur = 0;
#pragma unroll 1
            for (int tile = 0; tile < 32; tile++, cur ^= 1) {
                const int sbase = tile * 64;

                CP_WAIT0();
                __syncthreads();

                if (tile + 1 < 32) {
                    const int sbn = (tile + 1) * 64;
#pragma unroll
                    for (int i = 0; i < 4; i++) {
                        const int idx = tid + 256 * i;
                        const int row = idx >> 4;
                        const int c4  = (idx & 15) * 4;
                        cp_async16(mbuf_u32[cur ^ 1] + (uint)(row * BUFW + c4) * 4,
                                   m + ((size_t)r * SDIM + sbn + row) * CE + c4);
                    }
                    CP_COMMIT();
                }

                const float* buf = mbuf[cur];

                if (warp >= 4) {
                    const int prow = (warp - 4) * 16;
                    const int sg = sbase + prow + (lane & 15);
                    const float mskv = mask[(size_t)r * SDIM + sg];
                    if (lane < 16) mask_sh[sg] = mskv;
#pragma unroll 8
                    for (int i = 0; i < 16; i++) {
                        const float msk = __shfl_sync(0xffffffffu, mskv, i);
                        const ull mv = *(const ull*)&buf[(prow + i) * BUFW + 2 * lane];
                        ffma2(qn, mv, pack2(msk, msk));
                        qden += msk;
                    }
                } else {
                    const int rowbase = warp * 16;
                    float d[2][4];
#pragma unroll
                    for (int nt = 0; nt < 2; nt++)
#pragma unroll
                        for (int q = 0; q < 4; q++) d[nt][q] = 0.0f;

#pragma unroll
                    for (int kt = 0; kt < 4; kt++) {
                        uint ah[4], al[4];
                        {
                            const int r0 = rowbase + g;
                            const float2 f0 = *(const float2*)&buf[r0 * BUFW + 16 * kt + 2 * tg];
                            const float2 f1 = *(const float2*)&buf[(r0 + 8) * BUFW + 16 * kt + 2 * tg];
                            const float2 f2 = *(const float2*)&buf[r0 * BUFW + 16 * kt + 2 * tg + 8];
                            const float2 f3 = *(const float2*)&buf[(r0 + 8) * BUFW + 16 * kt + 2 * tg + 8];
                            split2(f0.x, f0.y, ah[0], al[0]);
                            split2(f1.x, f1.y, ah[1], al[1]);
                            split2(f2.x, f2.y, ah[2], al[2]);
                            split2(f3.x, f3.y, ah[3], al[3]);
                        }
#pragma unroll
                        for (int p = 0; p < 3; p++) {
                            const uint* wb = (p == 1) ? wkv_lo : wkv_hi;
                            const uint* af = (p == 2) ? al : ah;
#pragma unroll
                            for (int nt = 0; nt < 2; nt++) {
                                const uint b0 = wb[(nt * 8 + g) * ASTW + kt * 8 + tg];
                                const uint b1 = wb[(nt * 8 + g) * ASTW + kt * 8 + tg + 4];
                                mma_bf16(d[nt], af, b0, b1);
                            }
                        }
                    }

                    const int s0 = sbase + rowbase + g;
#pragma unroll
                    for (int nt = 0; nt < 2; nt++) {
                        const int cp = nt * 4 + tg;
                        kvp[cp * SDIM + s0]     = bfpack(d[nt][0], d[nt][1]);
                        kvp[cp * SDIM + s0 + 8] = bfpack(d[nt][2], d[nt][3]);
                    }
                }
            }

            if (warp >= 4) {
                ((ull*)qred)[(warp - 4) * 32 + lane] = qn;
                if (lane == 0) dred[warp - 4] = qden;
            }
            __syncthreads();

            if (tid < 64) {
                float qs = 0.0f;
#pragma unroll
                for (int w = 0; w < 4; w++) qs += qred[w * 64 + tid];
                float dt = 0.0f;
#pragma unroll
                for (int w = 0; w < 4; w++) dt += dred[w];
                qred[tid] = qs / (dt + 1e-10f);
            }
            __syncthreads();
            if (tid < 64) {
                float acc = 0.0f;
                const float* wqr = Wq + tid * 64;
#pragma unroll
                for (int e = 0; e < 64; e++) acc = fmaf(qred[e], wqr[e], acc);
                qproj[tid] = acc * QSCALE;
            }
            __syncthreads();

            const int h = warp;
            float qh[8];
#pragma unroll
            for (int c = 0; c < 8; c++) qh[c] = qproj[h * 8 + c];

            float mx = -1e30f;
#pragma unroll 1
            for (int i = 0; i < 64; i++) {
                const int s = lane + 32 * i;
                float lg = (mask_sh[s] - 1.0f) * 1e9f;
#pragma unroll
                for (int j = 0; j < 4; j++) {
                    const float2 kv2 = bf2f(kvp[j * SDIM + s]);
                    lg = fmaf(qh[2 * j], kv2.x, lg);
                    lg = fmaf(qh[2 * j + 1], kv2.y, lg);
                }
                mx = fmaxf(mx, lg);
            }
#pragma unroll
            for (int off = 16; off > 0; off >>= 1)
                mx = fmaxf(mx, __shfl_xor_sync(0xffffffffu, mx, off));

            float sum = 0.0f;
            float oacc[8];
#pragma unroll
            for (int c = 0; c < 8; c++) oacc[c] = 0.0f;
#pragma unroll 1
            for (int i = 0; i < 64; i++) {
                const int s = lane + 32 * i;
                float lg = (mask_sh[s] - 1.0f) * 1e9f;
#pragma unroll
                for (int j = 0; j < 4; j++) {
                    const float2 kv2 = bf2f(kvp[j * SDIM + s]);
                    lg = fmaf(qh[2 * j], kv2.x, lg);
                    lg = fmaf(qh[2 * j + 1], kv2.y, lg);
                }
                const float e = __expf(lg - mx);
                sum += e;
#pragma unroll
                for (int j = 0; j < 4; j++) {
                    const float2 vv = bf2f(kvp[(4 + j) * SDIM + s]);
                    oacc[2 * j]     = fmaf(e, vv.x, oacc[2 * j]);
                    oacc[2 * j + 1] = fmaf(e, vv.y, oacc[2 * j + 1]);
                }
            }
#pragma unroll
            for (int off = 16; off > 0; off >>= 1) {
                sum += __shfl_xor_sync(0xffffffffu, sum, off);
#pragma unroll
                for (int c = 0; c < 8; c++)
                    oacc[c] += __shfl_xor_sync(0xffffffffu, oacc[c], off);
            }
            if (lane == 0) {
                const float inv = 1.0f / sum;
#pragma unroll
                for (int c = 0; c < 8; c++)
                    g_o[r * HC + h * 8 + c] = oacc[c] * inv;
            }

            __threadfence();
            __syncthreads();
            if (tid == 0) g_flag[r] = 1;
            __syncthreads();
        }
    }

    // ======================= PHASE 2: gate tiles =======================
    __syncthreads();
    {
        float* gbuf[2] = { sfa + GB_MB, sfa + GB_MB + 128 * BUFW };
        uint* wg_hi = (uint*)(sfa + GB_W);
        uint* wo_hi = wg_hi + 64 * ASTW;
        float* bg_sh = sfa + GB_VEC;
        float* bo_sh = bg_sh + 64;
        int*   tshare = (int*)(sfa + GB_TS);
        const uint gbuf_u32[2] = { smem_u32(gbuf[0]), smem_u32(gbuf[1]) };

        for (int i = tid; i < 2048; i += 256) {
            const int row = i >> 5, kp = i & 31;
            {
                float2 w = *(const float2*)(Wg + row * 64 + kp * 2);
                wg_hi[row * ASTW + kp] = bfpack(w.x, w.y);
            }
            {
                float2 w = *(const float2*)(Wo + row * 64 + kp * 2);
                wo_hi[row * ASTW + kp] = bfpack(w.x, w.y);
            }
        }
        if (tid < 64) {
            bg_sh[tid] = bg[tid];
            bo_sh[tid] = bo[tid];
        }
        if (tid == 0) tshare[0] = atomicAdd(&g_ctr, 1);
        __syncthreads();

        int t = tshare[0];
        int cur = 0;
        if (t < G_NT) {
            const int r = t >> 4, sbase = (t & 15) * 128;
#pragma unroll
            for (int i = 0; i < 8; i++) {
                const int idx = tid + 256 * i;
                const int row = idx >> 4;
                const int c4  = (idx & 15) * 4;
                cp_async16(gbuf_u32[0] + (uint)(row * BUFW + c4) * 4,
                           m + ((size_t)r * SDIM + sbase + row) * CE + c4);
            }
            CP_COMMIT();
        }

#pragma unroll 1
        while (t < G_NT) {
            if (tid == 0) tshare[cur ^ 1] = atomicAdd(&g_ctr, 1);

            CP_WAIT0();
            __syncthreads();

            const int tn = tshare[cur ^ 1];
            if (tn < G_NT) {
                const int rn = tn >> 4, sbn = (tn & 15) * 128;
#pragma unroll
                for (int i = 0; i < 8; i++) {
                    const int idx = tid + 256 * i;
                    const int row = idx >> 4;
                    const int c4  = (idx & 15) * 4;
                    cp_async16(gbuf_u32[cur ^ 1] + (uint)(row * BUFW + c4) * 4,
                               m + ((size_t)rn * SDIM + sbn + row) * CE + c4);
                }
                CP_COMMIT();
            }

            const int r     = t >> 4;
            const int sbase = (t & 15) * 128;
            const float* buf = gbuf[cur];
            const int rowbase = warp * 16;
            float d[8][4];

            // GEMM1 (single bf16 product)
#pragma unroll
            for (int nt = 0; nt < 8; nt++)
#pragma unroll
                for (int q = 0; q < 4; q++) d[nt][q] = 0.0f;

#pragma unroll
            for (int kt = 0; kt < 4; kt++) {
                uint ah[4];
                {
                    const int r0 = rowbase + g;
                    const float2 f0 = *(const float2*)&buf[r0 * BUFW + 16 * kt + 2 * tg];
                    const float2 f1 = *(const float2*)&buf[(r0 + 8) * BUFW + 16 * kt + 2 * tg];
                    const float2 f2 = *(const float2*)&buf[r0 * BUFW + 16 * kt + 2 * tg + 8];
                    const float2 f3 = *(const float2*)&buf[(r0 + 8) * BUFW + 16 * kt + 2 * tg + 8];
                    ah[0] = bfpack(f0.x, f0.y);
                    ah[1] = bfpack(f1.x, f1.y);
                    ah[2] = bfpack(f2.x, f2.y);
                    ah[3] = bfpack(f3.x, f3.y);
                }
#pragma unroll
                for (int nt = 0; nt < 8; nt++) {
                    const uint b0 = wg_hi[(nt * 8 + g) * ASTW + kt * 8 + tg];
                    const uint b1 = wg_hi[(nt * 8 + g) * ASTW + kt * 8 + tg + 4];
                    mma_bf16(d[nt], ah, b0, b1);
                }
            }

            // wait for g_o[r] (producer CTA is guaranteed resident)
            while (g_flag[r] == 0) { __nanosleep(100); }
            __threadfence();

            // epilogue 1: t = sigmoid(d+bg)*o
            uint th[8][2];
#pragma unroll
            for (int nt = 0; nt < 8; nt++) {
                const int c0 = nt * 8 + tg * 2;
                const float ov0 = __ldg(&g_o[r * HC + c0]);
                const float ov1 = __ldg(&g_o[r * HC + c0 + 1]);
                const float bg0 = bg_sh[c0], bg1 = bg_sh[c0 + 1];
                const float t0v = fast_sigmoid(d[nt][0] + bg0) * ov0;
                const float t1v = fast_sigmoid(d[nt][1] + bg1) * ov1;
                const float t2v = fast_sigmoid(d[nt][2] + bg0) * ov0;
                const float t3v = fast_sigmoid(d[nt][3] + bg1) * ov1;
                th[nt][0] = bfpack(t0v, t1v);
                th[nt][1] = bfpack(t2v, t3v);
            }

            // GEMM2
#pragma unroll
            for (int nt = 0; nt < 8; nt++)
#pragma unroll
                for (int q = 0; q < 4; q++) d[nt][q] = 0.0f;

#pragma unroll
            for (int kt = 0; kt < 4; kt++) {
                uint a[4];
                a[0] = th[2 * kt][0];
                a[1] = th[2 * kt][1];
                a[2] = th[2 * kt + 1][0];
                a[3] = th[2 * kt + 1][1];
#pragma unroll
                for (int nt = 0; nt < 8; nt++) {
                    const uint b0 = wo_hi[(nt * 8 + g) * ASTW + kt * 8 + tg];
                    const uint b1 = wo_hi[(nt * 8 + g) * ASTW + kt * 8 + tg + 4];
                    mma_bf16(d[nt], a, b0, b1);
                }
            }

            // epilogue 2
#pragma unroll
            for (int nt = 0; nt < 8; nt++) {
                const int c0 = nt * 8 + tg * 2;
                const float bo0 = bo_sh[c0], bo1 = bo_sh[c0 + 1];
                const int r0 = rowbase + g;
                {
                    const size_t base = ((size_t)(sbase + r0) * RDIM + r) * CE + c0;
                    const float2 av = *(const float2*)(add_to + base);
                    float2 ov;
                    ov.x = d[nt][0] + bo0 + av.x;
                    ov.y = d[nt][1] + bo1 + av.y;
                    *(float2*)(out + base) = ov;
                }
                {
                    const size_t base = ((size_t)(sbase + r0 + 8) * RDIM + r) * CE + c0;
                    const float2 av = *(const float2*)(add_to + base);
                    float2 ov;
                    ov.x = d[nt][2] + bo0 + av.x;
                    ov.y = d[nt][3] + bo1 + av.y;
                    *(float2*)(out + base) = ov;
                }
            }

            t = tn;
            cur ^= 1;
        }
    }
}

// ============================================================================
extern "C" void kernel_launch(void* const* d_in, const int* in_sizes, int n_in,
                              void* d_out, int out_size) {
    const float* m      = (const float*)d_in[0];
    const float* mask   = (const float*)d_in[1];
    const float* Wq     = (const float*)d_in[2];
    const float* Wk     = (const float*)d_in[3];
    const float* Wv     = (const float*)d_in[4];
    const float* Wg     = (const float*)d_in[5];
    const float* bg     = (const float*)d_in[6];
    const float* Wo     = (const float*)d_in[7];
    const float* bo     = (const float*)d_in[8];
    const float* add_to = (const float*)d_in[9];
    float* out = (float*)d_out;

    cudaFuncSetAttribute(mega_kernel, cudaFuncAttributeMaxDynamicSharedMemorySize,
                         MG_SMEM_BYTES);

    reset_kernel<<<1, RDIM>>>();
    mega_kernel<<<MEGA_GRID, 256, MG_SMEM_BYTES>>>(m, mask, Wq, Wk, Wv,
                                                   Wg, bg, Wo, bo, add_to, out);
}